// round 4
// baseline (speedup 1.0000x reference)
#include <cuda_runtime.h>
#include <math_constants.h>

#define BB   32
#define NP   1024
#define KNN  20
#define NPTS (BB*NP)
#define NEDGE (NPTS*KNN)

typedef unsigned long long ull;

// packed f32x2 FMA: d.lo += a.lo*b.lo ; d.hi += a.hi*b.hi
__device__ __forceinline__ void fma2(ull& d, ull a, ull b) {
    asm("fma.rn.f32x2 %0, %1, %2, %0;" : "+l"(d) : "l"(a), "l"(b));
}
__device__ __forceinline__ float2 upk(ull v) {
    float2 r; asm("mov.b64 {%0,%1}, %2;" : "=f"(r.x), "=f"(r.y) : "l"(v)); return r;
}
__device__ __forceinline__ float fold(ull v) { float2 t = upk(v); return t.x + t.y; }

// ---------------- scratch ----------------
__device__ float g_D[(size_t)BB*NP*NP];
__device__ int   g_idx[NPTS*KNN];
__device__ float g_p1[NPTS*64];
__device__ float g_q1[NPTS*64];
__device__ float g_f1[NPTS*64];
__device__ float g_norm[NPTS];
__device__ float g_p2[NPTS*128];
__device__ float g_q2[NPTS*128];
__device__ float g_f2[NPTS*128];
__device__ float g_pool[BB*512];

// ---------------- 1) fused kNN on xyz ----------------
__global__ void __launch_bounds__(256) knn3_kernel(const float* __restrict__ x) {
    __shared__ float sx[NP], sy[NP], sz[NP], sq[NP];
    int rowBase = blockIdx.x * 8;
    int b = rowBase >> 10;
    const float* xb = x + (size_t)b * NP * 3;
    for (int i = threadIdx.x; i < NP; i += 256) {
        float a0 = xb[i*3], a1 = xb[i*3+1], a2 = xb[i*3+2];
        sx[i] = a0; sy[i] = a1; sz[i] = a2;
        sq[i] = a0*a0 + a1*a1 + a2*a2;
    }
    __syncthreads();
    int warp = threadIdx.x >> 5, lane = threadIdx.x & 31;
    int n  = rowBase + warp;
    int nl = n & (NP - 1);
    float qx = sx[nl], qy = sy[nl], qz = sz[nl], qs = sq[nl];
    float v[32];
#pragma unroll
    for (int i = 0; i < 32; i++) {
        int m = lane + (i << 5);
        float d = qs + sq[m] - 2.0f * (qx*sx[m] + qy*sy[m] + qz*sz[m]);
        v[i] = (m == nl) ? CUDART_INF_F : d;
    }
    float bv = v[0]; int bi = 0;
#pragma unroll
    for (int i = 1; i < 32; i++) if (v[i] < bv) { bv = v[i]; bi = i; }
    for (int r = 0; r < KNN; r++) {
        float mv = bv; int mi = (bi << 5) | lane;
#pragma unroll
        for (int off = 16; off > 0; off >>= 1) {
            float ov = __shfl_down_sync(0xffffffffu, mv, off);
            int   oi = __shfl_down_sync(0xffffffffu, mi, off);
            if (ov < mv || (ov == mv && oi < mi)) { mv = ov; mi = oi; }
        }
        mi = __shfl_sync(0xffffffffu, mi, 0);
        if (lane == 0) g_idx[n * KNN + r] = mi;
        if ((mi & 31) == lane) {
            int slot = mi >> 5;
#pragma unroll
            for (int i = 0; i < 32; i++) if (i == slot) v[i] = CUDART_INF_F;
            bv = v[0]; bi = 0;
#pragma unroll
            for (int i = 1; i < 32; i++) if (v[i] < bv) { bv = v[i]; bi = i; }
        }
    }
}

// ---------------- 2) top-20 per row of g_D (self excluded here) ------------
__global__ void topk_kernel() {
    int row  = blockIdx.x * 8 + (threadIdx.x >> 5);
    int lane = threadIdx.x & 31;
    int nl = row & (NP - 1);
    const float* d = g_D + (size_t)row * NP;
    float v[32];
#pragma unroll
    for (int i = 0; i < 32; i++) {
        int m = lane + (i << 5);
        v[i] = (m == nl) ? CUDART_INF_F : d[m];
    }
    float bv = v[0]; int bi = 0;
#pragma unroll
    for (int i = 1; i < 32; i++) if (v[i] < bv) { bv = v[i]; bi = i; }
    for (int r = 0; r < KNN; r++) {
        float mv = bv; int mi = (bi << 5) | lane;
#pragma unroll
        for (int off = 16; off > 0; off >>= 1) {
            float ov = __shfl_down_sync(0xffffffffu, mv, off);
            int   oi = __shfl_down_sync(0xffffffffu, mi, off);
            if (ov < mv || (ov == mv && oi < mi)) { mv = ov; mi = oi; }
        }
        mi = __shfl_sync(0xffffffffu, mi, 0);
        if (lane == 0) g_idx[row * KNN + r] = mi;
        if ((mi & 31) == lane) {
            int slot = mi >> 5;
#pragma unroll
            for (int i = 0; i < 32; i++) if (i == slot) v[i] = CUDART_INF_F;
            bv = v[0]; bi = 0;
#pragma unroll
            for (int i = 1; i < 32; i++) if (v[i] < bv) { bv = v[i]; bi = i; }
        }
    }
}

// ---------------- 3) EdgeConv1 layer-1 split precompute (+ zero f1) --------
__global__ void pre1_kernel(const float* __restrict__ x,
                            const float* __restrict__ W1,
                            const float* __restrict__ b1) {
    int id = blockIdx.x * blockDim.x + threadIdx.x;
    if (id >= NPTS * 64) return;
    int n = id >> 6, t = id & 63;
    float x0 = x[n*3], x1 = x[n*3+1], x2 = x[n*3+2];
    float wa0 = W1[t],       wa1 = W1[64 + t],  wa2 = W1[128 + t];
    float wb0 = W1[192 + t], wb1 = W1[256 + t], wb2 = W1[320 + t];
    float q = x0*wb0 + x1*wb1 + x2*wb2;
    float p = b1[t] + x0*(wa0-wb0) + x1*(wa1-wb1) + x2*(wa2-wb2);
    g_p1[id] = p;
    g_q1[id] = q;
    g_f1[id] = 0.0f;
}

// ---------------- 4) EdgeConv1: fused 2-layer GEMM, packed f32x2 -----------
// 128-edge tile, 64 ch. k-interleaved operands (even k in .lo, odd in .hi).
// smem bytes: ET2 33792 | W2i 16896 | W3i 16896 | b2 256 | b3 256
#define EP2 132
#define WP2 66
#define EC1_SMEM (33792 + 16896 + 16896 + 256 + 256)
__global__ void __launch_bounds__(256, 2) ec1_kernel(const float* __restrict__ W2,
                                                     const float* __restrict__ b2,
                                                     const float* __restrict__ W3,
                                                     const float* __restrict__ b3) {
    extern __shared__ float sm[];
    float* ETf  = sm;                         // 8448 floats
    ull*   ETu  = (ull*)sm;                   // float2 view, stride EP2
    ull*   W2u  = (ull*)(sm + 8448);          // [32][WP2]
    ull*   W3u  = (ull*)(sm + 8448 + 4224);
    float* sB2  = sm + 8448 + 8448;
    float* sB3  = sB2 + 64;
    int tid = threadIdx.x;
    int tx = tid & 7, ty = tid >> 3;          // cols tx*8..+7, rows(edges) ty*4..+3

    // weights k-interleaved: W_i[k2][j] = (W[2k2][j], W[2k2+1][j])
    for (int i = tid; i < 2048; i += 256) {
        int k2 = i >> 6, j = i & 63;
        float2 w2v = make_float2(W2[(2*k2)*64 + j], W2[(2*k2+1)*64 + j]);
        float2 w3v = make_float2(W3[(2*k2)*64 + j], W3[(2*k2+1)*64 + j]);
        *(float2*)(W2u + k2*WP2 + j) = w2v;
        *(float2*)(W3u + k2*WP2 + j) = w3v;
    }
    if (tid < 64) { sB2[tid] = b2[tid]; sB3[tid] = b3[tid]; }

    // build k-interleaved E^T: 2 threads per edge (32 channels each)
    int B0 = blockIdx.x * 128;
    {
        int e    = tid >> 1;
        int half = tid & 1;
        int g  = B0 + e;
        int p  = g / KNN;
        int bb = p >> 10;
        int j  = g_idx[g];
        const float* pr = g_p1 + (size_t)p * 64 + half*32;
        const float* qr = g_q1 + ((size_t)(bb << 10) + j) * 64 + half*32;
        float ev[32];
#pragma unroll
        for (int c = 0; c < 32; c += 4) {
            float4 pv = *(const float4*)(pr + c);
            float4 qv = *(const float4*)(qr + c);
            ev[c+0] = fmaxf(pv.x + qv.x, 0.0f);
            ev[c+1] = fmaxf(pv.y + qv.y, 0.0f);
            ev[c+2] = fmaxf(pv.z + qv.z, 0.0f);
            ev[c+3] = fmaxf(pv.w + qv.w, 0.0f);
        }
#pragma unroll
        for (int m = 0; m < 16; m++)
            *(float2*)(ETu + (half*16 + m)*EP2 + e) = make_float2(ev[2*m], ev[2*m+1]);
    }
    __syncthreads();

    ull acc[4][8];
    float h[4][8];

    // ---- layer 2 ----
#pragma unroll
    for (int r = 0; r < 4; r++)
#pragma unroll
        for (int c = 0; c < 8; c++) acc[r][c] = 0ULL;
#pragma unroll 8
    for (int k2 = 0; k2 < 32; k2++) {
        ulonglong2 a01 = *(const ulonglong2*)(ETu + k2*EP2 + ty*4);
        ulonglong2 a23 = *(const ulonglong2*)(ETu + k2*EP2 + ty*4 + 2);
        ulonglong2 w01 = *(const ulonglong2*)(W2u + k2*WP2 + tx*8);
        ulonglong2 w23 = *(const ulonglong2*)(W2u + k2*WP2 + tx*8 + 2);
        ulonglong2 w45 = *(const ulonglong2*)(W2u + k2*WP2 + tx*8 + 4);
        ulonglong2 w67 = *(const ulonglong2*)(W2u + k2*WP2 + tx*8 + 6);
        ull a[4] = {a01.x, a01.y, a23.x, a23.y};
        ull w[8] = {w01.x, w01.y, w23.x, w23.y, w45.x, w45.y, w67.x, w67.y};
#pragma unroll
        for (int r = 0; r < 4; r++)
#pragma unroll
            for (int c = 0; c < 8; c++) fma2(acc[r][c], a[r], w[c]);
    }
    {
        float bv[8];
#pragma unroll
        for (int c = 0; c < 8; c++) bv[c] = sB2[tx*8 + c];
#pragma unroll
        for (int r = 0; r < 4; r++)
#pragma unroll
            for (int c = 0; c < 8; c++) h[r][c] = fmaxf(fold(acc[r][c]) + bv[c], 0.0f);
    }
    __syncthreads();
    // restage H k-interleaved: k2' = tx*4+m over this thread's 8 channels
#pragma unroll
    for (int m = 0; m < 4; m++)
#pragma unroll
        for (int r = 0; r < 4; r++)
            *(float2*)(ETu + (tx*4 + m)*EP2 + (ty*4 + r)) = make_float2(h[r][2*m], h[r][2*m+1]);
    __syncthreads();

    // ---- layer 3 ----
#pragma unroll
    for (int r = 0; r < 4; r++)
#pragma unroll
        for (int c = 0; c < 8; c++) acc[r][c] = 0ULL;
#pragma unroll 8
    for (int k2 = 0; k2 < 32; k2++) {
        ulonglong2 a01 = *(const ulonglong2*)(ETu + k2*EP2 + ty*4);
        ulonglong2 a23 = *(const ulonglong2*)(ETu + k2*EP2 + ty*4 + 2);
        ulonglong2 w01 = *(const ulonglong2*)(W3u + k2*WP2 + tx*8);
        ulonglong2 w23 = *(const ulonglong2*)(W3u + k2*WP2 + tx*8 + 2);
        ulonglong2 w45 = *(const ulonglong2*)(W3u + k2*WP2 + tx*8 + 4);
        ulonglong2 w67 = *(const ulonglong2*)(W3u + k2*WP2 + tx*8 + 6);
        ull a[4] = {a01.x, a01.y, a23.x, a23.y};
        ull w[8] = {w01.x, w01.y, w23.x, w23.y, w45.x, w45.y, w67.x, w67.y};
#pragma unroll
        for (int r = 0; r < 4; r++)
#pragma unroll
            for (int c = 0; c < 8; c++) fma2(acc[r][c], a[r], w[c]);
    }
    {
        float bv[8];
#pragma unroll
        for (int c = 0; c < 8; c++) bv[c] = sB3[tx*8 + c];
        __syncthreads();       // ETu reads done; reuse as OUT[128][66]
#pragma unroll
        for (int r = 0; r < 4; r++)
#pragma unroll
            for (int m = 0; m < 4; m++) {
                float2 o = make_float2(fold(acc[r][2*m])   + bv[2*m],
                                       fold(acc[r][2*m+1]) + bv[2*m+1]);
                *(float2*)(ETf + (ty*4 + r)*66 + tx*8 + 2*m) = o;
            }
    }
    __syncthreads();

    // ---- per-point segmented max, atomicMax into f1 (0-init folds relu) ----
    int pFirst = B0 / KNN;
    int pLast  = (B0 + 127) / KNN;
    int nseg   = pLast - pFirst + 1;
    int ch = tid & 63;
    for (int s = tid >> 6; s < nseg; s += 4) {
        int pt = pFirst + s;
        int r0 = max(pt * KNN,       B0) - B0;
        int r1 = min(pt * KNN + KNN, B0 + 128) - B0;
        if (r0 >= r1) continue;
        float m = ETf[r0*66 + ch];
        for (int r = r0 + 1; r < r1; r++) m = fmaxf(m, ETf[r*66 + ch]);
        atomicMax((int*)&g_f1[(size_t)pt*64 + ch], __float_as_int(m));
    }
}

// ---------------- 4b) squared norms of f1 rows ------------------------------
__global__ void norm64_kernel() {
    int n = blockIdx.x * 256 + threadIdx.x;
    const float4* r = (const float4*)(g_f1 + (size_t)n * 64);
    float s = 0.0f;
#pragma unroll
    for (int i = 0; i < 16; i++) {
        float4 v = r[i];
        s += v.x*v.x + v.y*v.y + v.z*v.z + v.w*v.w;
    }
    g_norm[n] = s;
}

// ---------------- 5) dist64: Gram tile GEMM, packed f32x2 -------------------
// 512 thr, 128x128 tile, 8 rows x 4 cols per thread, K=64 in one smem stage.
#define D64_SMEM (33792 + 33792 + 512 + 512)
__global__ void __launch_bounds__(512, 1) dist64_kernel() {
    extern __shared__ float sm[];
    ull*   Au  = (ull*)sm;                    // [32][EP2] float2
    ull*   Bu  = (ull*)(sm + 8448);
    float* snA = sm + 16896;
    float* snB = snA + 128;
    int b  = blockIdx.z;
    int m0 = blockIdx.y * 128, n0 = blockIdx.x * 128;
    int tid = threadIdx.x;
    int tx = tid & 31, ty = tid >> 5;         // cols tx*4..+3, rows ty*8..+7
    const float* F = g_f1 + (size_t)b * NP * 64;

    // stage A,B k-interleaved: thread loads 32B (8 k) of one row
#pragma unroll
    for (int it = 0; it < 2; it++) {
        int idx = it * 512 + tid;
        int m = idx & 127, g = idx >> 7;      // g in 0..7
        const float4* ra = (const float4*)(F + (size_t)(m0 + m) * 64 + g*8);
        const float4* rb = (const float4*)(F + (size_t)(n0 + m) * 64 + g*8);
        float4 u = ra[0], v = ra[1];
        *(float2*)(Au + (4*g+0)*EP2 + m) = make_float2(u.x, u.y);
        *(float2*)(Au + (4*g+1)*EP2 + m) = make_float2(u.z, u.w);
        *(float2*)(Au + (4*g+2)*EP2 + m) = make_float2(v.x, v.y);
        *(float2*)(Au + (4*g+3)*EP2 + m) = make_float2(v.z, v.w);
        u = rb[0]; v = rb[1];
        *(float2*)(Bu + (4*g+0)*EP2 + m) = make_float2(u.x, u.y);
        *(float2*)(Bu + (4*g+1)*EP2 + m) = make_float2(u.z, u.w);
        *(float2*)(Bu + (4*g+2)*EP2 + m) = make_float2(v.x, v.y);
        *(float2*)(Bu + (4*g+3)*EP2 + m) = make_float2(v.z, v.w);
    }
    if (tid < 128)       snA[tid]       = g_norm[b*NP + m0 + tid];
    else if (tid < 256)  snB[tid - 128] = g_norm[b*NP + n0 + tid - 128];
    __syncthreads();

    ull acc[8][4];
#pragma unroll
    for (int i = 0; i < 8; i++)
#pragma unroll
        for (int j = 0; j < 4; j++) acc[i][j] = 0ULL;

#pragma unroll 8
    for (int k2 = 0; k2 < 32; k2++) {
        ulonglong2 a01 = *(const ulonglong2*)(Au + k2*EP2 + ty*8);
        ulonglong2 a23 = *(const ulonglong2*)(Au + k2*EP2 + ty*8 + 2);
        ulonglong2 a45 = *(const ulonglong2*)(Au + k2*EP2 + ty*8 + 4);
        ulonglong2 a67 = *(const ulonglong2*)(Au + k2*EP2 + ty*8 + 6);
        ulonglong2 b01 = *(const ulonglong2*)(Bu + k2*EP2 + tx*4);
        ulonglong2 b23 = *(const ulonglong2*)(Bu + k2*EP2 + tx*4 + 2);
        ull a[8] = {a01.x, a01.y, a23.x, a23.y, a45.x, a45.y, a67.x, a67.y};
        ull c[4] = {b01.x, b01.y, b23.x, b23.y};
#pragma unroll
        for (int i = 0; i < 8; i++)
#pragma unroll
            for (int j = 0; j < 4; j++) fma2(acc[i][j], a[i], c[j]);
    }

    float* Dp = g_D + (size_t)b * NP * NP;
    float nb_[4];
#pragma unroll
    for (int j = 0; j < 4; j++) nb_[j] = snB[tx*4 + j];
#pragma unroll
    for (int i = 0; i < 8; i++) {
        float nai = snA[ty*8 + i];
        float4 o;
        o.x = nai + nb_[0] - 2.0f * fold(acc[i][0]);
        o.y = nai + nb_[1] - 2.0f * fold(acc[i][1]);
        o.z = nai + nb_[2] - 2.0f * fold(acc[i][2]);
        o.w = nai + nb_[3] - 2.0f * fold(acc[i][3]);
        *(float4*)(Dp + (size_t)(m0 + ty*8 + i) * NP + n0 + tx*4) = o;
    }
}

// ---------------- 6) EdgeConv2 layer split precompute -----------------------
#define PRE2_SMEM ((8192 + 8192 + 4096) * 4)
__global__ void pre2_kernel(const float* __restrict__ W4,
                            const float* __restrict__ b4) {
    extern __shared__ float sm[];
    float* sWd = sm;
    float* sWb = sm + 8192;
    float* sF  = sm + 16384;
    int tid = threadIdx.x;
    int base = blockIdx.x * 64;
    for (int i = tid; i < 8192; i += 256) {
        int c = i >> 7, t = i & 127;
        float wa = W4[c * 128 + t];
        float wb = W4[(64 + c) * 128 + t];
        sWd[i] = wa - wb;
        sWb[i] = wb;
    }
    for (int i = tid; i < 4096; i += 256) sF[i] = g_f1[(size_t)base * 64 + i];
    __syncthreads();
    int t = tid & 127, half = tid >> 7;
    float bias = b4[t];
    for (int pp = 0; pp < 32; pp++) {
        int lp = (pp << 1) + half;
        const float* fr = sF + lp * 64;
        float accp = bias, accq = 0.0f;
#pragma unroll 8
        for (int c = 0; c < 64; c++) {
            float f = fr[c];
            accp = fmaf(f, sWd[c * 128 + t], accp);
            accq = fmaf(f, sWb[c * 128 + t], accq);
        }
        g_p2[(size_t)(base + lp) * 128 + t] = accp;
        g_q2[(size_t)(base + lp) * 128 + t] = accq;
    }
}

// ---------------- 7) EdgeConv2: max_k relu(p + q) ---------------------------
__global__ void ec2_kernel() {
    int n = blockIdx.x, t = threadIdx.x;
    int b = n >> 10;
    float p = g_p2[(size_t)n * 128 + t];
    const int* idxp = g_idx + n * KNN;
    float best = 0.0f;
#pragma unroll
    for (int k = 0; k < KNN; k++) {
        int j = idxp[k];
        float q = g_q2[((size_t)(b << 10) + j) * 128 + t];
        best = fmaxf(best, p + q);
    }
    g_f2[(size_t)n * 128 + t] = best;
}

// ---------------- 8) pool: relu(f2@Wp+bp) + max over points (f32x2 GEMM) ---
__global__ void zero_pool_kernel() {
    int i = blockIdx.x * blockDim.x + threadIdx.x;
    if (i < BB * 512) g_pool[i] = 0.0f;
}

#define POOL_SMEM (33792 + 33792 + 8192)
__global__ void __launch_bounds__(512, 1) pool_kernel(const float* __restrict__ Wp,
                                                      const float* __restrict__ bp) {
    extern __shared__ float sm[];
    ull*   Au   = (ull*)sm;                   // f2 tile  [32][EP2]
    ull*   Bu   = (ull*)(sm + 8448);          // Wp tile
    float* sred = sm + 16896;                 // [16][128]
    int m0 = blockIdx.x * 128, n0 = blockIdx.y * 128;
    int b  = m0 >> 10;
    int tid = threadIdx.x;
    int tx = tid & 31, ty = tid >> 5;         // cols tx*4..+3, rows ty*8..+7

    ull acc[8][4];
#pragma unroll
    for (int i = 0; i < 8; i++)
#pragma unroll
        for (int j = 0; j < 4; j++) acc[i][j] = 0ULL;

    for (int kc = 0; kc < 2; kc++) {
        __syncthreads();
#pragma unroll
        for (int it = 0; it < 2; it++) {
            int idx = it * 512 + tid;
            int m = idx & 127, g = idx >> 7;
            const float4* ra = (const float4*)(g_f2 + (size_t)(m0 + m) * 128 + kc*64 + g*8);
            float4 u = ra[0], v = ra[1];
            *(float2*)(Au + (4*g+0)*EP2 + m) = make_float2(u.x, u.y);
            *(float2*)(Au + (4*g+1)*EP2 + m) = make_float2(u.z, u.w);
            *(float2*)(Au + (4*g+2)*EP2 + m) = make_float2(v.x, v.y);
            *(float2*)(Au + (4*g+3)*EP2 + m) = make_float2(v.z, v.w);
        }
#pragma unroll
        for (int it = 0; it < 8; it++) {
            int idx = it * 512 + tid;
            int n = idx & 127, k2 = idx >> 7;
            float w0 = Wp[(size_t)(kc*64 + 2*k2)     * 512 + n0 + n];
            float w1 = Wp[(size_t)(kc*64 + 2*k2 + 1) * 512 + n0 + n];
            *(float2*)(Bu + k2*EP2 + n) = make_float2(w0, w1);
        }
        __syncthreads();
#pragma unroll 8
        for (int k2 = 0; k2 < 32; k2++) {
            ulonglong2 a01 = *(const ulonglong2*)(Au + k2*EP2 + ty*8);
            ulonglong2 a23 = *(const ulonglong2*)(Au + k2*EP2 + ty*8 + 2);
            ulonglong2 a45 = *(const ulonglong2*)(Au + k2*EP2 + ty*8 + 4);
            ulonglong2 a67 = *(const ulonglong2*)(Au + k2*EP2 + ty*8 + 6);
            ulonglong2 b01 = *(const ulonglong2*)(Bu + k2*EP2 + tx*4);
            ulonglong2 b23 = *(const ulonglong2*)(Bu + k2*EP2 + tx*4 + 2);
            ull a[8] = {a01.x, a01.y, a23.x, a23.y, a45.x, a45.y, a67.x, a67.y};
            ull c[4] = {b01.x, b01.y, b23.x, b23.y};
#pragma unroll
            for (int i = 0; i < 8; i++)
#pragma unroll
                for (int j = 0; j < 4; j++) fma2(acc[i][j], a[i], c[j]);
        }
    }
    // bias + relu + row-max within thread, then cross-thread reduce
#pragma unroll
    for (int j = 0; j < 4; j++) {
        int col = n0 + tx*4 + j;
        float bpv = bp[col];
        float cm = 0.0f;
#pragma unroll
        for (int i = 0; i < 8; i++) cm = fmaxf(cm, fold(acc[i][j]) + bpv);
        sred[ty * 128 + tx*4 + j] = cm;
    }
    __syncthreads();
    if (ty == 0) {
#pragma unroll
        for (int j = 0; j < 4; j++) {
            float cm = 0.0f;
#pragma unroll
            for (int yy = 0; yy < 16; yy++) cm = fmaxf(cm, sred[yy * 128 + tx*4 + j]);
            atomicMax((int*)&g_pool[b * 512 + n0 + tx*4 + j], __float_as_int(cm));
        }
    }
}

// ---------------- 9) classifier head ----------------------------------------
__global__ void head_kernel(const float* __restrict__ Wt1, const float* __restrict__ bt1,
                            const float* __restrict__ Wt2, const float* __restrict__ bt2,
                            float* __restrict__ out) {
    __shared__ float sp[512];
    __shared__ float st[256];
    int b = blockIdx.x, t = threadIdx.x;
    sp[t]       = g_pool[b * 512 + t];
    sp[256 + t] = g_pool[b * 512 + 256 + t];
    __syncthreads();
    float acc = bt1[t];
#pragma unroll 8
    for (int c = 0; c < 512; c++) acc = fmaf(sp[c], Wt1[c * 256 + t], acc);
    st[t] = fmaxf(acc, 0.0f);
    __syncthreads();
    if (t < 40) {
        float a2 = bt2[t];
#pragma unroll 8
        for (int c = 0; c < 256; c++) a2 = fmaf(st[c], Wt2[c * 40 + t], a2);
        out[b * 40 + t] = a2;
    }
}

// ---------------- launch -----------------------------------------------------
extern "C" void kernel_launch(void* const* d_in, const int* in_sizes, int n_in,
                              void* d_out, int out_size) {
    const float* x   = (const float*)d_in[0];
    const float* W1  = (const float*)d_in[2];
    const float* b1  = (const float*)d_in[3];
    const float* W2  = (const float*)d_in[4];
    const float* b2  = (const float*)d_in[5];
    const float* W3  = (const float*)d_in[6];
    const float* b3  = (const float*)d_in[7];
    const float* W4  = (const float*)d_in[8];
    const float* b4  = (const float*)d_in[9];
    const float* Wp  = (const float*)d_in[10];
    const float* bp  = (const float*)d_in[11];
    const float* Wt1 = (const float*)d_in[12];
    const float* bt1 = (const float*)d_in[13];
    const float* Wt2 = (const float*)d_in[14];
    const float* bt2 = (const float*)d_in[15];
    float* out = (float*)d_out;

    cudaFuncSetAttribute(ec1_kernel,    cudaFuncAttributeMaxDynamicSharedMemorySize, EC1_SMEM);
    cudaFuncSetAttribute(dist64_kernel, cudaFuncAttributeMaxDynamicSharedMemorySize, D64_SMEM);
    cudaFuncSetAttribute(pre2_kernel,   cudaFuncAttributeMaxDynamicSharedMemorySize, PRE2_SMEM);
    cudaFuncSetAttribute(pool_kernel,   cudaFuncAttributeMaxDynamicSharedMemorySize, POOL_SMEM);

    // Stage 1
    knn3_kernel<<<NPTS / 8, 256>>>(x);
    pre1_kernel<<<(NPTS * 64) / 256, 256>>>(x, W1, b1);
    ec1_kernel<<<NEDGE / 128, 256, EC1_SMEM>>>(W2, b2, W3, b3);

    // Stage 2
    norm64_kernel<<<NPTS / 256, 256>>>();
    dist64_kernel<<<dim3(8, 8, BB), 512, D64_SMEM>>>();
    topk_kernel<<<NPTS / 8, 256>>>();
    pre2_kernel<<<NPTS / 64, 256, PRE2_SMEM>>>(W4, b4);
    ec2_kernel<<<NPTS, 128>>>();

    // Stage 3
    zero_pool_kernel<<<16, 1024>>>();
    pool_kernel<<<dim3(256, 4), 512, POOL_SMEM>>>(Wp, bp);
    head_kernel<<<BB, 256>>>(Wt1, bt1, Wt2, bt2, out);
}

// round 5
// speedup vs baseline: 1.3535x; 1.3535x over previous
#include <cuda_runtime.h>
#include <math_constants.h>

#define BB   32
#define NP   1024
#define KNN  20
#define NPTS (BB*NP)
#define NEDGE (NPTS*KNN)

// ---------------- scratch (device globals; no allocation allowed) ----------
__device__ float g_D[(size_t)BB*NP*NP];
__device__ int   g_idx[NPTS*KNN];
__device__ float g_p1[NPTS*64];
__device__ float g_q1[NPTS*64];
__device__ float g_f1[NPTS*64];
__device__ float g_norm[NPTS];
__device__ float g_p2[NPTS*128];
__device__ float g_q2[NPTS*128];
__device__ float g_f2[NPTS*128];
__device__ float g_pool[BB*512];

// ---------------- 1) fused kNN on xyz ----------------
__global__ void __launch_bounds__(256) knn3_kernel(const float* __restrict__ x) {
    __shared__ float sx[NP], sy[NP], sz[NP], sq[NP];
    int rowBase = blockIdx.x * 8;
    int b = rowBase >> 10;
    const float* xb = x + (size_t)b * NP * 3;
    for (int i = threadIdx.x; i < NP; i += 256) {
        float a0 = xb[i*3], a1 = xb[i*3+1], a2 = xb[i*3+2];
        sx[i] = a0; sy[i] = a1; sz[i] = a2;
        sq[i] = a0*a0 + a1*a1 + a2*a2;
    }
    __syncthreads();
    int warp = threadIdx.x >> 5, lane = threadIdx.x & 31;
    int n  = rowBase + warp;
    int nl = n & (NP - 1);
    float qx = sx[nl], qy = sy[nl], qz = sz[nl], qs = sq[nl];
    float v[32];
#pragma unroll
    for (int i = 0; i < 32; i++) {
        int m = lane + (i << 5);
        float d = qs + sq[m] - 2.0f * (qx*sx[m] + qy*sy[m] + qz*sz[m]);
        v[i] = (m == nl) ? CUDART_INF_F : d;
    }
    float bv = v[0]; int bi = 0;
#pragma unroll
    for (int i = 1; i < 32; i++) if (v[i] < bv) { bv = v[i]; bi = i; }
    for (int r = 0; r < KNN; r++) {
        float mv = bv; int mi = (bi << 5) | lane;
#pragma unroll
        for (int off = 16; off > 0; off >>= 1) {
            float ov = __shfl_down_sync(0xffffffffu, mv, off);
            int   oi = __shfl_down_sync(0xffffffffu, mi, off);
            if (ov < mv || (ov == mv && oi < mi)) { mv = ov; mi = oi; }
        }
        mi = __shfl_sync(0xffffffffu, mi, 0);
        if (lane == 0) g_idx[n * KNN + r] = mi;
        if ((mi & 31) == lane) {
            int slot = mi >> 5;
#pragma unroll
            for (int i = 0; i < 32; i++) if (i == slot) v[i] = CUDART_INF_F;
            bv = v[0]; bi = 0;
#pragma unroll
            for (int i = 1; i < 32; i++) if (v[i] < bv) { bv = v[i]; bi = i; }
        }
    }
}

// ---------------- 2) top-20 per row of g_D (self excluded here) ------------
__global__ void topk_kernel() {
    int row  = blockIdx.x * 8 + (threadIdx.x >> 5);
    int lane = threadIdx.x & 31;
    int nl = row & (NP - 1);
    const float* d = g_D + (size_t)row * NP;
    float v[32];
#pragma unroll
    for (int i = 0; i < 32; i++) {
        int m = lane + (i << 5);
        v[i] = (m == nl) ? CUDART_INF_F : d[m];
    }
    float bv = v[0]; int bi = 0;
#pragma unroll
    for (int i = 1; i < 32; i++) if (v[i] < bv) { bv = v[i]; bi = i; }
    for (int r = 0; r < KNN; r++) {
        float mv = bv; int mi = (bi << 5) | lane;
#pragma unroll
        for (int off = 16; off > 0; off >>= 1) {
            float ov = __shfl_down_sync(0xffffffffu, mv, off);
            int   oi = __shfl_down_sync(0xffffffffu, mi, off);
            if (ov < mv || (ov == mv && oi < mi)) { mv = ov; mi = oi; }
        }
        mi = __shfl_sync(0xffffffffu, mi, 0);
        if (lane == 0) g_idx[row * KNN + r] = mi;
        if ((mi & 31) == lane) {
            int slot = mi >> 5;
#pragma unroll
            for (int i = 0; i < 32; i++) if (i == slot) v[i] = CUDART_INF_F;
            bv = v[0]; bi = 0;
#pragma unroll
            for (int i = 1; i < 32; i++) if (v[i] < bv) { bv = v[i]; bi = i; }
        }
    }
}

// ---------------- 3) EdgeConv1 layer-1 split precompute (+ zero f1) --------
__global__ void pre1_kernel(const float* __restrict__ x,
                            const float* __restrict__ W1,
                            const float* __restrict__ b1) {
    int id = blockIdx.x * blockDim.x + threadIdx.x;
    if (id >= NPTS * 64) return;
    int n = id >> 6, t = id & 63;
    float x0 = x[n*3], x1 = x[n*3+1], x2 = x[n*3+2];
    float wa0 = W1[t],       wa1 = W1[64 + t],  wa2 = W1[128 + t];
    float wb0 = W1[192 + t], wb1 = W1[256 + t], wb2 = W1[320 + t];
    float q = x0*wb0 + x1*wb1 + x2*wb2;
    float p = b1[t] + x0*(wa0-wb0) + x1*(wa1-wb1) + x2*(wa2-wb2);
    g_p1[id] = p;
    g_q1[id] = q;
    g_f1[id] = 0.0f;
}

// ---------------- 4) EdgeConv1 fused 2-layer GEMM over 256-edge tiles ------
#define ETP 260
#define EC1_SMEM ((64*ETP + 4096 + 4096 + 64 + 64) * 4)
__global__ void __launch_bounds__(256, 2) ec1_kernel(const float* __restrict__ W2,
                                                     const float* __restrict__ b2,
                                                     const float* __restrict__ W3,
                                                     const float* __restrict__ b3) {
    extern __shared__ float sm[];
    float* ET  = sm;
    float* sW2 = sm + 64*ETP;
    float* sW3 = sW2 + 4096;
    float* sB2 = sW3 + 4096;
    float* sB3 = sB2 + 64;
    int tid = threadIdx.x;
    int tx = tid & 7, ty = tid >> 3;

    for (int i = tid; i < 4096; i += 256) { sW2[i] = W2[i]; sW3[i] = W3[i]; }
    if (tid < 64) { sB2[tid] = b2[tid]; sB3[tid] = b3[tid]; }

    int B0 = blockIdx.x * 256;
    int g  = B0 + tid;
    int p  = g / KNN;
    int b  = p >> 10;
    int j  = g_idx[g];
    const float* pr = g_p1 + (size_t)p * 64;
    const float* qr = g_q1 + ((size_t)(b << 10) + j) * 64;
    __syncthreads();
#pragma unroll
    for (int c = 0; c < 64; c += 4) {
        float4 pv = *(const float4*)(pr + c);
        float4 qv = *(const float4*)(qr + c);
        ET[(c+0)*ETP + tid] = fmaxf(pv.x + qv.x, 0.0f);
        ET[(c+1)*ETP + tid] = fmaxf(pv.y + qv.y, 0.0f);
        ET[(c+2)*ETP + tid] = fmaxf(pv.z + qv.z, 0.0f);
        ET[(c+3)*ETP + tid] = fmaxf(pv.w + qv.w, 0.0f);
    }
    __syncthreads();

    float acc[8][8];
#pragma unroll
    for (int i = 0; i < 8; i++)
#pragma unroll
        for (int jj = 0; jj < 8; jj++) acc[i][jj] = 0.0f;
#pragma unroll 4
    for (int k = 0; k < 64; k++) {
        float4 a0 = *(const float4*)(ET + k*ETP + ty*8);
        float4 a1 = *(const float4*)(ET + k*ETP + ty*8 + 4);
        float4 w0 = *(const float4*)(sW2 + k*64 + tx*8);
        float4 w1 = *(const float4*)(sW2 + k*64 + tx*8 + 4);
        float a[8] = {a0.x,a0.y,a0.z,a0.w,a1.x,a1.y,a1.z,a1.w};
        float w[8] = {w0.x,w0.y,w0.z,w0.w,w1.x,w1.y,w1.z,w1.w};
#pragma unroll
        for (int i = 0; i < 8; i++)
#pragma unroll
            for (int jj = 0; jj < 8; jj++) acc[i][jj] = fmaf(a[i], w[jj], acc[i][jj]);
    }
    float bv2[8], bv3[8];
#pragma unroll
    for (int jj = 0; jj < 8; jj++) { bv2[jj] = sB2[tx*8+jj]; bv3[jj] = sB3[tx*8+jj]; }
    __syncthreads();
#pragma unroll
    for (int jj = 0; jj < 8; jj++)
#pragma unroll
        for (int i = 0; i < 8; i++)
            ET[(tx*8+jj)*ETP + ty*8 + i] = fmaxf(acc[i][jj] + bv2[jj], 0.0f);
    __syncthreads();

#pragma unroll
    for (int i = 0; i < 8; i++)
#pragma unroll
        for (int jj = 0; jj < 8; jj++) acc[i][jj] = 0.0f;
#pragma unroll 4
    for (int k = 0; k < 64; k++) {
        float4 a0 = *(const float4*)(ET + k*ETP + ty*8);
        float4 a1 = *(const float4*)(ET + k*ETP + ty*8 + 4);
        float4 w0 = *(const float4*)(sW3 + k*64 + tx*8);
        float4 w1 = *(const float4*)(sW3 + k*64 + tx*8 + 4);
        float a[8] = {a0.x,a0.y,a0.z,a0.w,a1.x,a1.y,a1.z,a1.w};
        float w[8] = {w0.x,w0.y,w0.z,w0.w,w1.x,w1.y,w1.z,w1.w};
#pragma unroll
        for (int i = 0; i < 8; i++)
#pragma unroll
            for (int jj = 0; jj < 8; jj++) acc[i][jj] = fmaf(a[i], w[jj], acc[i][jj]);
    }
    __syncthreads();
#pragma unroll
    for (int i = 0; i < 8; i++) {
        float4 v0, v1;
        v0.x = acc[i][0] + bv3[0]; v0.y = acc[i][1] + bv3[1];
        v0.z = acc[i][2] + bv3[2]; v0.w = acc[i][3] + bv3[3];
        v1.x = acc[i][4] + bv3[4]; v1.y = acc[i][5] + bv3[5];
        v1.z = acc[i][6] + bv3[6]; v1.w = acc[i][7] + bv3[7];
        *(float4*)(ET + (ty*8+i)*64 + tx*8)     = v0;
        *(float4*)(ET + (ty*8+i)*64 + tx*8 + 4) = v1;
    }
    __syncthreads();

    int pFirst = B0 / KNN;
    int pLast  = (B0 + 255) / KNN;
    int nseg   = pLast - pFirst + 1;
    int ch = tid & 63;
    for (int s = tid >> 6; s < nseg; s += 4) {
        int pt = pFirst + s;
        int r0 = max(pt * KNN,       B0) - B0;
        int r1 = min(pt * KNN + KNN, B0 + 256) - B0;
        if (r0 >= r1) continue;
        float m = ET[r0*64 + ch];
        for (int r = r0 + 1; r < r1; r++) m = fmaxf(m, ET[r*64 + ch]);
        atomicMax((int*)&g_f1[(size_t)pt*64 + ch], __float_as_int(m));
    }
}

// ---------------- 4b) squared norms of f1 rows ------------------------------
__global__ void norm64_kernel() {
    int n = blockIdx.x * 256 + threadIdx.x;
    const float4* r = (const float4*)(g_f1 + (size_t)n * 64);
    float s = 0.0f;
#pragma unroll
    for (int i = 0; i < 16; i++) {
        float4 v = r[i];
        s += v.x*v.x + v.y*v.y + v.z*v.z + v.w*v.w;
    }
    g_norm[n] = s;
}

// ---------------- 5) dist64: Gram GEMM, norms hoisted, float4 stores --------
#define TS 132
#define D64_SMEM ((32*TS*2 + 256) * 4)
__global__ void __launch_bounds__(256) dist64_kernel() {
    extern __shared__ float sm[];
    float* sAt = sm;                 // [k][m] transposed tiles
    float* sBt = sm + 32*TS;
    float* snA = sm + 64*TS;
    float* snB = snA + 128;
    int b  = blockIdx.z;
    int m0 = blockIdx.y * 128, n0 = blockIdx.x * 128;
    int tid = threadIdx.x;
    int tx = tid & 15, ty = tid >> 4;
    const float* F = g_f1 + (size_t)b * NP * 64;

    if (tid < 128)      snA[tid]       = g_norm[b*NP + m0 + tid];
    else                snB[tid - 128] = g_norm[b*NP + n0 + tid - 128];

    float acc[8][8];
#pragma unroll
    for (int i = 0; i < 8; i++)
#pragma unroll
        for (int j = 0; j < 8; j++) acc[i][j] = 0.0f;

    for (int kc = 0; kc < 2; kc++) {
        __syncthreads();
#pragma unroll
        for (int l = 0; l < 16; l++) {
            int idx = l * 256 + tid;
            int r = idx >> 5, c = idx & 31;
            sAt[c * TS + r] = F[(size_t)(m0 + r) * 64 + kc * 32 + c];
            sBt[c * TS + r] = F[(size_t)(n0 + r) * 64 + kc * 32 + c];
        }
        __syncthreads();
        for (int k = 0; k < 32; k++) {
            float4 a0 = *(const float4*)(sAt + k * TS + ty * 8);
            float4 a1 = *(const float4*)(sAt + k * TS + ty * 8 + 4);
            float4 c0 = *(const float4*)(sBt + k * TS + tx * 8);
            float4 c1 = *(const float4*)(sBt + k * TS + tx * 8 + 4);
            float a[8]  = {a0.x, a0.y, a0.z, a0.w, a1.x, a1.y, a1.z, a1.w};
            float bv[8] = {c0.x, c0.y, c0.z, c0.w, c1.x, c1.y, c1.z, c1.w};
#pragma unroll
            for (int i = 0; i < 8; i++)
#pragma unroll
                for (int j = 0; j < 8; j++) acc[i][j] = fmaf(a[i], bv[j], acc[i][j]);
        }
    }
    float* Dp = g_D + (size_t)b * NP * NP;
    float nb_[8];
#pragma unroll
    for (int j = 0; j < 8; j++) nb_[j] = snB[tx*8 + j];
#pragma unroll
    for (int i = 0; i < 8; i++) {
        float nai = snA[ty*8 + i];
        float4 o0, o1;
        o0.x = nai + nb_[0] - 2.0f * acc[i][0];
        o0.y = nai + nb_[1] - 2.0f * acc[i][1];
        o0.z = nai + nb_[2] - 2.0f * acc[i][2];
        o0.w = nai + nb_[3] - 2.0f * acc[i][3];
        o1.x = nai + nb_[4] - 2.0f * acc[i][4];
        o1.y = nai + nb_[5] - 2.0f * acc[i][5];
        o1.z = nai + nb_[6] - 2.0f * acc[i][6];
        o1.w = nai + nb_[7] - 2.0f * acc[i][7];
        float* row = Dp + (size_t)(m0 + ty*8 + i) * NP + n0 + tx*8;
        *(float4*)row       = o0;
        *(float4*)(row + 4) = o1;
    }
}

// ---------------- 6) pre2 as GEMM: [p2|q2] = f1 @ [W4a-W4b | W4b] ----------
// grid (2, 256): blockIdx.x = 0 -> p2 (+b4), 1 -> q2. 128x128 tile, K=64.
#define PRE2_SMEM ((32*TS*2 + 128) * 4)
__global__ void __launch_bounds__(256) pre2_kernel(const float* __restrict__ W4,
                                                   const float* __restrict__ b4) {
    extern __shared__ float sm[];
    float* sAt = sm;                 // f1 tile [k][m]
    float* sBt = sm + 32*TS;         // weight tile [k][n]
    float* sBias = sm + 64*TS;
    int nblk = blockIdx.x;           // 0 = p-half, 1 = q-half
    int m0 = blockIdx.y * 128;
    int tid = threadIdx.x;
    int tx = tid & 15, ty = tid >> 4;

    if (tid < 128) sBias[tid] = (nblk == 0) ? b4[tid] : 0.0f;

    float acc[8][8];
#pragma unroll
    for (int i = 0; i < 8; i++)
#pragma unroll
        for (int j = 0; j < 8; j++) acc[i][j] = 0.0f;

    for (int kc = 0; kc < 2; kc++) {
        __syncthreads();
#pragma unroll
        for (int l = 0; l < 16; l++) {
            int idx = l * 256 + tid;
            int r = idx >> 5, c = idx & 31;
            sAt[c * TS + r] = g_f1[(size_t)(m0 + r) * 64 + kc * 32 + c];
        }
#pragma unroll
        for (int l = 0; l < 16; l++) {
            int idx = l * 256 + tid;
            int nl = idx & 127, kk = idx >> 7;
            int k = kc * 32 + kk;
            float wb = W4[(64 + k) * 128 + nl];
            float w  = (nblk == 0) ? (W4[k * 128 + nl] - wb) : wb;
            sBt[kk * TS + nl] = w;
        }
        __syncthreads();
        for (int k = 0; k < 32; k++) {
            float4 a0 = *(const float4*)(sAt + k * TS + ty * 8);
            float4 a1 = *(const float4*)(sAt + k * TS + ty * 8 + 4);
            float4 c0 = *(const float4*)(sBt + k * TS + tx * 8);
            float4 c1 = *(const float4*)(sBt + k * TS + tx * 8 + 4);
            float a[8]  = {a0.x, a0.y, a0.z, a0.w, a1.x, a1.y, a1.z, a1.w};
            float bv[8] = {c0.x, c0.y, c0.z, c0.w, c1.x, c1.y, c1.z, c1.w};
#pragma unroll
            for (int i = 0; i < 8; i++)
#pragma unroll
                for (int j = 0; j < 8; j++) acc[i][j] = fmaf(a[i], bv[j], acc[i][j]);
        }
    }
    float* dst = (nblk == 0) ? g_p2 : g_q2;
    float bb[8];
#pragma unroll
    for (int j = 0; j < 8; j++) bb[j] = sBias[tx*8 + j];
#pragma unroll
    for (int i = 0; i < 8; i++) {
        float4 o0, o1;
        o0.x = acc[i][0] + bb[0]; o0.y = acc[i][1] + bb[1];
        o0.z = acc[i][2] + bb[2]; o0.w = acc[i][3] + bb[3];
        o1.x = acc[i][4] + bb[4]; o1.y = acc[i][5] + bb[5];
        o1.z = acc[i][6] + bb[6]; o1.w = acc[i][7] + bb[7];
        float* row = dst + (size_t)(m0 + ty*8 + i) * 128 + tx*8;
        *(float4*)row       = o0;
        *(float4*)(row + 4) = o1;
    }
}

// ---------------- 7) EdgeConv2: max_k relu(p + q) ---------------------------
__global__ void ec2_kernel() {
    int n = blockIdx.x, t = threadIdx.x;
    int b = n >> 10;
    float p = g_p2[(size_t)n * 128 + t];
    const int* idxp = g_idx + n * KNN;
    float best = 0.0f;
#pragma unroll
    for (int k = 0; k < KNN; k++) {
        int j = idxp[k];
        float q = g_q2[((size_t)(b << 10) + j) * 128 + t];
        best = fmaxf(best, p + q);
    }
    g_f2[(size_t)n * 128 + t] = best;
}

// ---------------- 8) pool: relu(f2@Wp+bp), max over points -----------------
__global__ void zero_pool_kernel() {
    int i = blockIdx.x * blockDim.x + threadIdx.x;
    if (i < BB * 512) g_pool[i] = 0.0f;
}

__global__ void pool_kernel(const float* __restrict__ Wp,
                            const float* __restrict__ bp) {
    __shared__ float sAt[32 * TS];
    __shared__ float sBt[32 * TS];
    __shared__ float sred[16 * 128];
    int m0 = blockIdx.x * 128, n0 = blockIdx.y * 128;
    int b  = m0 >> 10;
    int tid = threadIdx.x;
    int tx = tid & 15, ty = tid >> 4;

    float acc[8][8];
#pragma unroll
    for (int i = 0; i < 8; i++)
#pragma unroll
        for (int j = 0; j < 8; j++) acc[i][j] = 0.0f;

    for (int kc = 0; kc < 4; kc++) {
        __syncthreads();
#pragma unroll
        for (int l = 0; l < 16; l++) {
            int idx = l * 256 + tid;
            int r = idx >> 5, c = idx & 31;
            sAt[c * TS + r] = g_f2[(size_t)(m0 + r) * 128 + kc * 32 + c];
        }
#pragma unroll
        for (int l = 0; l < 16; l++) {
            int idx = l * 256 + tid;
            int nl = idx & 127, kk = idx >> 7;
            sBt[kk * TS + nl] = Wp[(size_t)(kc * 32 + kk) * 512 + n0 + nl];
        }
        __syncthreads();
        for (int k = 0; k < 32; k++) {
            float4 a0 = *(const float4*)(sAt + k * TS + ty * 8);
            float4 a1 = *(const float4*)(sAt + k * TS + ty * 8 + 4);
            float4 c0 = *(const float4*)(sBt + k * TS + tx * 8);
            float4 c1 = *(const float4*)(sBt + k * TS + tx * 8 + 4);
            float a[8]  = {a0.x, a0.y, a0.z, a0.w, a1.x, a1.y, a1.z, a1.w};
            float bv[8] = {c0.x, c0.y, c0.z, c0.w, c1.x, c1.y, c1.z, c1.w};
#pragma unroll
            for (int i = 0; i < 8; i++)
#pragma unroll
                for (int j = 0; j < 8; j++) acc[i][j] = fmaf(a[i], bv[j], acc[i][j]);
        }
    }
#pragma unroll
    for (int j = 0; j < 8; j++) {
        int col = n0 + tx * 8 + j;
        float bpv = bp[col];
        float cm = 0.0f;
#pragma unroll
        for (int i = 0; i < 8; i++) cm = fmaxf(cm, acc[i][j] + bpv);
        sred[ty * 128 + tx * 8 + j] = cm;
    }
    __syncthreads();
    if (ty == 0) {
#pragma unroll
        for (int j = 0; j < 8; j++) {
            float cm = 0.0f;
#pragma unroll
            for (int yy = 0; yy < 16; yy++) cm = fmaxf(cm, sred[yy * 128 + tx * 8 + j]);
            atomicMax((int*)&g_pool[b * 512 + n0 + tx * 8 + j], __float_as_int(cm));
        }
    }
}

// ---------------- 9) classifier head ----------------------------------------
__global__ void head_kernel(const float* __restrict__ Wt1, const float* __restrict__ bt1,
                            const float* __restrict__ Wt2, const float* __restrict__ bt2,
                            float* __restrict__ out) {
    __shared__ float sp[512];
    __shared__ float st[256];
    int b = blockIdx.x, t = threadIdx.x;
    sp[t]       = g_pool[b * 512 + t];
    sp[256 + t] = g_pool[b * 512 + 256 + t];
    __syncthreads();
    float acc = bt1[t];
#pragma unroll 8
    for (int c = 0; c < 512; c++) acc = fmaf(sp[c], Wt1[c * 256 + t], acc);
    st[t] = fmaxf(acc, 0.0f);
    __syncthreads();
    if (t < 40) {
        float a2 = bt2[t];
#pragma unroll 8
        for (int c = 0; c < 256; c++) a2 = fmaf(st[c], Wt2[c * 40 + t], a2);
        out[b * 40 + t] = a2;
    }
}

// ---------------- launch -----------------------------------------------------
extern "C" void kernel_launch(void* const* d_in, const int* in_sizes, int n_in,
                              void* d_out, int out_size) {
    const float* x   = (const float*)d_in[0];
    const float* W1  = (const float*)d_in[2];
    const float* b1  = (const float*)d_in[3];
    const float* W2  = (const float*)d_in[4];
    const float* b2  = (const float*)d_in[5];
    const float* W3  = (const float*)d_in[6];
    const float* b3  = (const float*)d_in[7];
    const float* W4  = (const float*)d_in[8];
    const float* b4  = (const float*)d_in[9];
    const float* Wp  = (const float*)d_in[10];
    const float* bp  = (const float*)d_in[11];
    const float* Wt1 = (const float*)d_in[12];
    const float* bt1 = (const float*)d_in[13];
    const float* Wt2 = (const float*)d_in[14];
    const float* bt2 = (const float*)d_in[15];
    float* out = (float*)d_out;

    cudaFuncSetAttribute(ec1_kernel,    cudaFuncAttributeMaxDynamicSharedMemorySize, EC1_SMEM);
    cudaFuncSetAttribute(dist64_kernel, cudaFuncAttributeMaxDynamicSharedMemorySize, D64_SMEM);
    cudaFuncSetAttribute(pre2_kernel,   cudaFuncAttributeMaxDynamicSharedMemorySize, PRE2_SMEM);

    // Stage 1
    knn3_kernel<<<NPTS / 8, 256>>>(x);
    pre1_kernel<<<(NPTS * 64) / 256, 256>>>(x, W1, b1);
    ec1_kernel<<<NEDGE / 256, 256, EC1_SMEM>>>(W2, b2, W3, b3);

    // Stage 2
    norm64_kernel<<<NPTS / 256, 256>>>();
    dist64_kernel<<<dim3(8, 8, BB), 256, D64_SMEM>>>();
    topk_kernel<<<NPTS / 8, 256>>>();
    pre2_kernel<<<dim3(2, 256), 256, PRE2_SMEM>>>(W4, b4);
    ec2_kernel<<<NPTS, 128>>>();

    // Stage 3
    zero_pool_kernel<<<16, 1024>>>();
    pool_kernel<<<dim3(256, 4), 256>>>(Wp, bp);
    head_kernel<<<BB, 256>>>(Wt1, bt1, Wt2, bt2, out);
}